// round 9
// baseline (speedup 1.0000x reference)
#include <cuda_runtime.h>

#define B_   2
#define N_   2048
#define E_   512
#define H_   8
#define D_   64
#define ROWS (B_ * N_)   // 4096

// -------- scratch (__device__ globals; no allocations allowed) --------
__device__ float g_QK[ROWS * 1024];          // [row][0..511]=Q, [512..1023]=K  (16 MB)
__device__ float g_xs[B_ * E_];              // sum of x rows 3..N-1 per batch
__device__ float g_V4[B_ * H_ * 4 * D_];     // v0,v1,v2,vz per (b,h)
__device__ float g_U[B_ * 32 * E_];          // U[b][h*4+k][e]
__device__ float g_coef[ROWS * 32];          // a0,a1,a2,az per (b,h,r)

// ---------------- Kernel A: fused QK GEMM  QK = x @ [Wq;Wk]^T + bias --------
// M=4096, Ncols=1024 (first 512 from Wq, next 512 from Wk), K=512
__global__ __launch_bounds__(256, 2)
void gemm_qk_kernel(const float* __restrict__ x,
                    const float* __restrict__ Wq, const float* __restrict__ bq,
                    const float* __restrict__ Wk, const float* __restrict__ bk) {
    __shared__ float As[16][132];
    __shared__ float Bs[16][132];
    const int col0  = blockIdx.x * 128;            // 0..1023
    const int row0  = blockIdx.y * 128;
    const float* W  = (col0 < 512) ? Wq : Wk;
    const float* bb = (col0 < 512) ? bq : bk;
    const int wrow0 = col0 & 511;
    const int tid = threadIdx.x;
    const int tx  = tid & 15;        // 0..15  -> output cols tx*8..tx*8+7
    const int ty  = tid >> 4;        // 0..15  -> output rows ty*8..ty*8+7
    const int lm  = tid >> 2;        // 0..63  load row within tile
    const int lk  = (tid & 3) * 4;   // 0,4,8,12 load k offset

    float acc[8][8];
    #pragma unroll
    for (int i = 0; i < 8; ++i)
        #pragma unroll
        for (int j = 0; j < 8; ++j) acc[i][j] = 0.f;

    for (int kt = 0; kt < 512; kt += 16) {
        #pragma unroll
        for (int p = 0; p < 2; ++p) {
            int m = lm + p * 64;
            float4 a = *(const float4*)&x[(size_t)(row0 + m) * 512 + kt + lk];
            As[lk + 0][m] = a.x; As[lk + 1][m] = a.y;
            As[lk + 2][m] = a.z; As[lk + 3][m] = a.w;
            float4 w = *(const float4*)&W[(size_t)(wrow0 + m) * 512 + kt + lk];
            Bs[lk + 0][m] = w.x; Bs[lk + 1][m] = w.y;
            Bs[lk + 2][m] = w.z; Bs[lk + 3][m] = w.w;
        }
        __syncthreads();
        #pragma unroll
        for (int k = 0; k < 16; ++k) {
            float a[8], b[8];
            #pragma unroll
            for (int i = 0; i < 8; ++i) a[i] = As[k][ty * 8 + i];
            #pragma unroll
            for (int j = 0; j < 8; ++j) b[j] = Bs[k][tx * 8 + j];
            #pragma unroll
            for (int i = 0; i < 8; ++i)
                #pragma unroll
                for (int j = 0; j < 8; ++j)
                    acc[i][j] = fmaf(a[i], b[j], acc[i][j]);
        }
        __syncthreads();
    }

    // epilogue: add bias, vectorized store
    float4 bias0 = *(const float4*)&bb[wrow0 + tx * 8];
    float4 bias1 = *(const float4*)&bb[wrow0 + tx * 8 + 4];
    #pragma unroll
    for (int i = 0; i < 8; ++i) {
        size_t r = (size_t)(row0 + ty * 8 + i);
        float4 o0, o1;
        o0.x = acc[i][0] + bias0.x; o0.y = acc[i][1] + bias0.y;
        o0.z = acc[i][2] + bias0.z; o0.w = acc[i][3] + bias0.w;
        o1.x = acc[i][4] + bias1.x; o1.y = acc[i][5] + bias1.y;
        o1.z = acc[i][6] + bias1.z; o1.w = acc[i][7] + bias1.w;
        *(float4*)&g_QK[r * 1024 + col0 + tx * 8]     = o0;
        *(float4*)&g_QK[r * 1024 + col0 + tx * 8 + 4] = o1;
    }
}

// ---------------- Kernel B: zero + row-sum of x over rows 3..N-1 ------------
__global__ void zero_xs_kernel() {
    g_xs[blockIdx.x * 512 + threadIdx.x] = 0.f;
}

__global__ void xsum_kernel(const float* __restrict__ x) {
    int b  = blockIdx.x;
    int e  = blockIdx.y * 128 + threadIdx.x;
    int r0 = 3 + blockIdx.z * 256;
    int r1 = min(r0 + 256, N_);
    float s = 0.f;
    for (int r = r0; r < r1; ++r)
        s += x[((size_t)b * N_ + r) * E_ + e];
    atomicAdd(&g_xs[b * E_ + e], s);
}

// ---------------- Kernel C1: v0,v1,v2,vz per (b,h) --------------------------
__global__ void v4_kernel(const float* __restrict__ x,
                          const float* __restrict__ Wv, const float* __restrict__ bv) {
    int b = blockIdx.x >> 3, h = blockIdx.x & 7;
    int k = threadIdx.x >> 6, d = threadIdx.x & 63;   // 4*64 = 256 threads
    int wr = h * 64 + d;
    const float* wrow = Wv + (size_t)wr * 512;
    const float* xr = (k < 3) ? (x + ((size_t)b * N_ + k) * E_)
                              : (g_xs + (size_t)b * E_);
    float s = (k < 3) ? bv[wr] : (float)(N_ - 3) * bv[wr];
    for (int i = 0; i < 512; i += 4) {
        float4 xa = *(const float4*)&xr[i];
        float4 wa = *(const float4*)&wrow[i];
        s += xa.x * wa.x + xa.y * wa.y + xa.z * wa.z + xa.w * wa.w;
    }
    g_V4[((b * 8 + h) * 4 + k) * 64 + d] = s;
}

// ---------------- Kernel C2: U[b][h*4+k][e] = Wo[e, h*64: ] . v_k -----------
__global__ void u_kernel(const float* __restrict__ Wo) {
    int b = blockIdx.x >> 3, h = blockIdx.x & 7;
    __shared__ float sv[256];
    sv[threadIdx.x] = g_V4[(b * 8 + h) * 256 + threadIdx.x];
    __syncthreads();
    for (int e = threadIdx.x; e < 512; e += 256) {
        const float* wo = Wo + (size_t)e * 512 + h * 64;
        float s0 = 0.f, s1 = 0.f, s2 = 0.f, s3 = 0.f;
        #pragma unroll
        for (int d = 0; d < 64; ++d) {
            float w = wo[d];
            s0 = fmaf(w, sv[d],       s0);
            s1 = fmaf(w, sv[64 + d],  s1);
            s2 = fmaf(w, sv[128 + d], s2);
            s3 = fmaf(w, sv[192 + d], s3);
        }
        float* up = g_U + ((size_t)b * 32 + h * 4) * 512 + e;
        up[0] = s0; up[512] = s1; up[1024] = s2; up[1536] = s3;
    }
}

// ---------------- Kernel D: scores + softmax coefficients -------------------
// one warp per (b,h,r)
__global__ void score_kernel() {
    int warp = threadIdx.x >> 5, lane = threadIdx.x & 31;
    int idx = blockIdx.x * 8 + warp;                 // (b*H + h)*N + r
    int r = idx & (N_ - 1);
    int h = (idx >> 11) & 7;
    int b = idx >> 14;
    size_t row = (size_t)b * N_ + r;
    const float* qb = g_QK + row * 1024 + h * 64;
    float q0 = qb[lane], q1 = qb[lane + 32];
    float s[3];
    #pragma unroll
    for (int t = 0; t < 3; ++t) {
        int rk = r + t - 1;
        float v = 0.f;
        if (rk >= 0 && rk < N_) {
            const float* kb = g_QK + ((size_t)b * N_ + rk) * 1024 + 512 + h * 64;
            v = q0 * kb[lane] + q1 * kb[lane + 32];
        }
        #pragma unroll
        for (int o = 16; o; o >>= 1) v += __shfl_xor_sync(0xffffffffu, v, o);
        s[t] = v;
    }
    if (lane == 0) {
        float m  = fmaxf(fmaxf(s[0], s[1]), fmaxf(s[2], 0.f));
        float e0 = __expf(s[0] - m), e1 = __expf(s[1] - m);
        float e2 = __expf(s[2] - m), ez = __expf(-m);
        float inv = 1.f / (e0 + e1 + e2 + (float)(N_ - 3) * ez);
        float* cp = g_coef + row * 32 + h * 4;
        cp[0] = e0 * inv; cp[1] = e1 * inv; cp[2] = e2 * inv; cp[3] = ez * inv;
    }
}

// ---------------- Kernel E: y = bo + coef @ U --------------------------------
// block = 512 threads (one per output column e), 16 rows per block
__global__ __launch_bounds__(512)
void final_kernel(const float* __restrict__ bo, float* __restrict__ out) {
    int b  = blockIdx.x >> 7;            // 128 row-tiles per batch
    int r0 = (blockIdx.x & 127) * 16;
    int e  = threadIdx.x;
    float u[32];
    #pragma unroll
    for (int j = 0; j < 32; ++j)
        u[j] = g_U[((size_t)b * 32 + j) * 512 + e];
    __shared__ float sc[512];            // 16 rows x 32 coefs
    sc[threadIdx.x] = g_coef[((size_t)b * N_ + r0) * 32 + threadIdx.x];
    __syncthreads();
    float bb = bo[e];
    #pragma unroll 4
    for (int rr = 0; rr < 16; ++rr) {
        float y = bb;
        #pragma unroll
        for (int j = 0; j < 32; ++j)
            y = fmaf(sc[rr * 32 + j], u[j], y);
        out[((size_t)b * N_ + r0 + rr) * 512 + e] = y;
    }
}

// ---------------- launch -----------------------------------------------------
extern "C" void kernel_launch(void* const* d_in, const int* in_sizes, int n_in,
                              void* d_out, int out_size) {
    const float* x  = (const float*)d_in[0];
    const float* Wq = (const float*)d_in[1];
    const float* bq = (const float*)d_in[2];
    const float* Wk = (const float*)d_in[3];
    const float* bk = (const float*)d_in[4];
    const float* Wv = (const float*)d_in[5];
    const float* bv = (const float*)d_in[6];
    const float* Wo = (const float*)d_in[7];
    const float* bo = (const float*)d_in[8];
    float* out = (float*)d_out;

    gemm_qk_kernel<<<dim3(8, 32), 256>>>(x, Wq, bq, Wk, bk);   // dominant cost
    zero_xs_kernel<<<2, 512>>>();
    xsum_kernel<<<dim3(2, 4, 8), 128>>>(x);
    v4_kernel<<<16, 256>>>(x, Wv, bv);
    u_kernel<<<16, 256>>>(Wo);
    score_kernel<<<4096, 256>>>();
    final_kernel<<<256, 512>>>(bo, out);
}

// round 10
// speedup vs baseline: 1.0098x; 1.0098x over previous
#include <cuda_runtime.h>

#define B_   2
#define N_   2048
#define E_   512
#define H_   8
#define D_   64
#define ROWS (B_ * N_)   // 4096

// -------- scratch (__device__ globals; no allocations allowed) --------
__device__ float g_QK[ROWS * 1024];          // [row][0..511]=Q, [512..1023]=K  (16 MB)
__device__ float g_xs[B_ * E_];              // sum of x rows 3..N-1 per batch
__device__ float g_V4[B_ * H_ * 4 * D_];     // v0,v1,v2,vz per (b,h)
__device__ float g_U[B_ * 32 * E_];          // U[b][h*4+k][e]
__device__ float g_coef[ROWS * 32];          // a0,a1,a2,az per (b,h,r)

// ---------------- Kernel A: fused QK GEMM  QK = x @ [Wq;Wk]^T + bias --------
// M=4096, Ncols=1024 (first 512 from Wq, next 512 from Wk), K=512
__global__ __launch_bounds__(256, 2)
void gemm_qk_kernel(const float* __restrict__ x,
                    const float* __restrict__ Wq, const float* __restrict__ bq,
                    const float* __restrict__ Wk, const float* __restrict__ bk) {
    __shared__ float As[16][132];
    __shared__ float Bs[16][132];
    const int col0  = blockIdx.x * 128;            // 0..1023
    const int row0  = blockIdx.y * 128;
    const float* W  = (col0 < 512) ? Wq : Wk;
    const float* bb = (col0 < 512) ? bq : bk;
    const int wrow0 = col0 & 511;
    const int tid = threadIdx.x;
    const int tx  = tid & 15;        // 0..15  -> output cols tx*8..tx*8+7
    const int ty  = tid >> 4;        // 0..15  -> output rows ty*8..ty*8+7
    const int lm  = tid >> 2;        // 0..63  load row within tile
    const int lk  = (tid & 3) * 4;   // 0,4,8,12 load k offset

    float acc[8][8];
    #pragma unroll
    for (int i = 0; i < 8; ++i)
        #pragma unroll
        for (int j = 0; j < 8; ++j) acc[i][j] = 0.f;

    for (int kt = 0; kt < 512; kt += 16) {
        #pragma unroll
        for (int p = 0; p < 2; ++p) {
            int m = lm + p * 64;
            float4 a = *(const float4*)&x[(size_t)(row0 + m) * 512 + kt + lk];
            As[lk + 0][m] = a.x; As[lk + 1][m] = a.y;
            As[lk + 2][m] = a.z; As[lk + 3][m] = a.w;
            float4 w = *(const float4*)&W[(size_t)(wrow0 + m) * 512 + kt + lk];
            Bs[lk + 0][m] = w.x; Bs[lk + 1][m] = w.y;
            Bs[lk + 2][m] = w.z; Bs[lk + 3][m] = w.w;
        }
        __syncthreads();
        #pragma unroll
        for (int k = 0; k < 16; ++k) {
            float a[8], b[8];
            #pragma unroll
            for (int i = 0; i < 8; ++i) a[i] = As[k][ty * 8 + i];
            #pragma unroll
            for (int j = 0; j < 8; ++j) b[j] = Bs[k][tx * 8 + j];
            #pragma unroll
            for (int i = 0; i < 8; ++i)
                #pragma unroll
                for (int j = 0; j < 8; ++j)
                    acc[i][j] = fmaf(a[i], b[j], acc[i][j]);
        }
        __syncthreads();
    }

    // epilogue: add bias, vectorized store
    float4 bias0 = *(const float4*)&bb[wrow0 + tx * 8];
    float4 bias1 = *(const float4*)&bb[wrow0 + tx * 8 + 4];
    #pragma unroll
    for (int i = 0; i < 8; ++i) {
        size_t r = (size_t)(row0 + ty * 8 + i);
        float4 o0, o1;
        o0.x = acc[i][0] + bias0.x; o0.y = acc[i][1] + bias0.y;
        o0.z = acc[i][2] + bias0.z; o0.w = acc[i][3] + bias0.w;
        o1.x = acc[i][4] + bias1.x; o1.y = acc[i][5] + bias1.y;
        o1.z = acc[i][6] + bias1.z; o1.w = acc[i][7] + bias1.w;
        *(float4*)&g_QK[r * 1024 + col0 + tx * 8]     = o0;
        *(float4*)&g_QK[r * 1024 + col0 + tx * 8 + 4] = o1;
    }
}

// ---------------- Kernel B: zero + row-sum of x over rows 3..N-1 ------------
__global__ void zero_xs_kernel() {
    g_xs[blockIdx.x * 512 + threadIdx.x] = 0.f;
}

__global__ void xsum_kernel(const float* __restrict__ x) {
    int b  = blockIdx.x;
    int e  = blockIdx.y * 128 + threadIdx.x;
    int r0 = 3 + blockIdx.z * 256;
    int r1 = min(r0 + 256, N_);
    float s = 0.f;
    for (int r = r0; r < r1; ++r)
        s += x[((size_t)b * N_ + r) * E_ + e];
    atomicAdd(&g_xs[b * E_ + e], s);
}

// ---------------- Kernel C1: v0,v1,v2,vz per (b,h) --------------------------
__global__ void v4_kernel(const float* __restrict__ x,
                          const float* __restrict__ Wv, const float* __restrict__ bv) {
    int b = blockIdx.x >> 3, h = blockIdx.x & 7;
    int k = threadIdx.x >> 6, d = threadIdx.x & 63;   // 4*64 = 256 threads
    int wr = h * 64 + d;
    const float* wrow = Wv + (size_t)wr * 512;
    const float* xr = (k < 3) ? (x + ((size_t)b * N_ + k) * E_)
                              : (g_xs + (size_t)b * E_);
    float s = (k < 3) ? bv[wr] : (float)(N_ - 3) * bv[wr];
    for (int i = 0; i < 512; i += 4) {
        float4 xa = *(const float4*)&xr[i];
        float4 wa = *(const float4*)&wrow[i];
        s += xa.x * wa.x + xa.y * wa.y + xa.z * wa.z + xa.w * wa.w;
    }
    g_V4[((b * 8 + h) * 4 + k) * 64 + d] = s;
}

// ---------------- Kernel C2: U[b][h*4+k][e] = Wo[e, h*64: ] . v_k -----------
__global__ void u_kernel(const float* __restrict__ Wo) {
    int b = blockIdx.x >> 3, h = blockIdx.x & 7;
    __shared__ float sv[256];
    sv[threadIdx.x] = g_V4[(b * 8 + h) * 256 + threadIdx.x];
    __syncthreads();
    for (int e = threadIdx.x; e < 512; e += 256) {
        const float* wo = Wo + (size_t)e * 512 + h * 64;
        float s0 = 0.f, s1 = 0.f, s2 = 0.f, s3 = 0.f;
        #pragma unroll
        for (int d = 0; d < 64; ++d) {
            float w = wo[d];
            s0 = fmaf(w, sv[d],       s0);
            s1 = fmaf(w, sv[64 + d],  s1);
            s2 = fmaf(w, sv[128 + d], s2);
            s3 = fmaf(w, sv[192 + d], s3);
        }
        float* up = g_U + ((size_t)b * 32 + h * 4) * 512 + e;
        up[0] = s0; up[512] = s1; up[1024] = s2; up[1536] = s3;
    }
}

// ---------------- Kernel D: scores + softmax coefficients -------------------
// one warp per (b,h,r)
__global__ void score_kernel() {
    int warp = threadIdx.x >> 5, lane = threadIdx.x & 31;
    int idx = blockIdx.x * 8 + warp;                 // (b*H + h)*N + r
    int r = idx & (N_ - 1);
    int h = (idx >> 11) & 7;
    int b = idx >> 14;
    size_t row = (size_t)b * N_ + r;
    const float* qb = g_QK + row * 1024 + h * 64;
    float q0 = qb[lane], q1 = qb[lane + 32];
    float s[3];
    #pragma unroll
    for (int t = 0; t < 3; ++t) {
        int rk = r + t - 1;
        float v = 0.f;
        if (rk >= 0 && rk < N_) {
            const float* kb = g_QK + ((size_t)b * N_ + rk) * 1024 + 512 + h * 64;
            v = q0 * kb[lane] + q1 * kb[lane + 32];
        }
        #pragma unroll
        for (int o = 16; o; o >>= 1) v += __shfl_xor_sync(0xffffffffu, v, o);
        s[t] = v;
    }
    if (lane == 0) {
        float m  = fmaxf(fmaxf(s[0], s[1]), fmaxf(s[2], 0.f));
        float e0 = __expf(s[0] - m), e1 = __expf(s[1] - m);
        float e2 = __expf(s[2] - m), ez = __expf(-m);
        float inv = 1.f / (e0 + e1 + e2 + (float)(N_ - 3) * ez);
        float* cp = g_coef + row * 32 + h * 4;
        cp[0] = e0 * inv; cp[1] = e1 * inv; cp[2] = e2 * inv; cp[3] = ez * inv;
    }
}

// ---------------- Kernel E: y = bo + coef @ U --------------------------------
// block = 512 threads (one per output column e), 16 rows per block
__global__ __launch_bounds__(512)
void final_kernel(const float* __restrict__ bo, float* __restrict__ out) {
    int b  = blockIdx.x >> 7;            // 128 row-tiles per batch
    int r0 = (blockIdx.x & 127) * 16;
    int e  = threadIdx.x;
    float u[32];
    #pragma unroll
    for (int j = 0; j < 32; ++j)
        u[j] = g_U[((size_t)b * 32 + j) * 512 + e];
    __shared__ float sc[512];            // 16 rows x 32 coefs
    sc[threadIdx.x] = g_coef[((size_t)b * N_ + r0) * 32 + threadIdx.x];
    __syncthreads();
    float bb = bo[e];
    #pragma unroll 4
    for (int rr = 0; rr < 16; ++rr) {
        float y = bb;
        #pragma unroll
        for (int j = 0; j < 32; ++j)
            y = fmaf(sc[rr * 32 + j], u[j], y);
        out[((size_t)b * N_ + r0 + rr) * 512 + e] = y;
    }
}

// ---------------- launch -----------------------------------------------------
extern "C" void kernel_launch(void* const* d_in, const int* in_sizes, int n_in,
                              void* d_out, int out_size) {
    const float* x  = (const float*)d_in[0];
    const float* Wq = (const float*)d_in[1];
    const float* bq = (const float*)d_in[2];
    const float* Wk = (const float*)d_in[3];
    const float* bk = (const float*)d_in[4];
    const float* Wv = (const float*)d_in[5];
    const float* bv = (const float*)d_in[6];
    const float* Wo = (const float*)d_in[7];
    const float* bo = (const float*)d_in[8];
    float* out = (float*)d_out;

    gemm_qk_kernel<<<dim3(8, 32), 256>>>(x, Wq, bq, Wk, bk);   // dominant cost
    zero_xs_kernel<<<2, 512>>>();
    xsum_kernel<<<dim3(2, 4, 8), 128>>>(x);
    v4_kernel<<<16, 256>>>(x, Wv, bv);
    u_kernel<<<16, 256>>>(Wo);
    score_kernel<<<4096, 256>>>();
    final_kernel<<<256, 512>>>(bo, out);
}